// round 3
// baseline (speedup 1.0000x reference)
#include <cuda_runtime.h>
#include <cstdint>
#include <cstddef>

#define NNODES 50000
#define NEDGES 800000
#define NREL   8
#define DIM    128
#define LNEPS  1e-5f
#define BM     64

// ---------------- scratch (device globals; no allocation allowed) ----------------
__device__ float g_xA[(size_t)NNODES * DIM];                 // 25.6 MB
__device__ float g_xB[(size_t)NNODES * DIM];                 // 25.6 MB
__device__ float g_agg[(size_t)NNODES * NREL * DIM];         // 204.8 MB
__device__ float g_cnt[(size_t)NNODES * NREL];               // 1.6 MB

// ---------------- utility kernels ----------------
// Zeroes agg (n4a float4's) and cnt (n4c float4's) in one launch.
__global__ void zero2_kernel(float4* __restrict__ a, int n4a,
                             float4* __restrict__ c, int n4c) {
    int i = blockIdx.x * blockDim.x + threadIdx.x;
    float4 z = make_float4(0.f, 0.f, 0.f, 0.f);
    if (i < n4a) a[i] = z;
    else if (i - n4a < n4c) c[i - n4a] = z;
}

__global__ void gather_kernel(const int* __restrict__ ids,
                              const float4* __restrict__ emb,
                              float4* __restrict__ x) {
    int i = blockIdx.x * blockDim.x + threadIdx.x;
    if (i >= NNODES * (DIM / 4)) return;
    int row = i >> 5;        // 32 float4 per row
    int c   = i & 31;
    x[(size_t)row * 32 + c] = emb[(size_t)ids[row] * 32 + c];
}

// One warp per edge: read 128 floats of x[src] (L2-resident), vector-reduce into agg.
__global__ void scatter_kernel(const float* __restrict__ x,
                               const int* __restrict__ ei,
                               const int* __restrict__ et) {
    int t = blockIdx.x * blockDim.x + threadIdx.x;
    int e = t >> 5;
    if (e >= NEDGES) return;
    int lane = t & 31;
    int src = ei[e];
    int dst = ei[NEDGES + e];
    int r   = et[e];
    size_t seg = (size_t)dst * NREL + r;
    float4 v = *(const float4*)(x + (size_t)src * DIM + lane * 4);
    float* p = g_agg + seg * DIM + lane * 4;
    asm volatile("red.global.add.v4.f32 [%0], {%1,%2,%3,%4};"
                 :: "l"(p), "f"(v.x), "f"(v.y), "f"(v.z), "f"(v.w) : "memory");
    if (lane == 0) atomicAdd(g_cnt + seg, 1.0f);
}

// ---------------- fused RGCN GEMM (+ optional LayerNorm+ReLU epilogue) ----------------
// out[n, :] = sum_{r<8} (agg[n,r,:]/max(cnt,1)) @ W[r] + x[n,:] @ root + bias
// Block: 64 rows x 128 cols. 256 threads; each thread 4 rows x 8 cols.
// Inner product uses packed fma.rn.f32x2 (2 cols per instruction).
template <bool LN>
__global__ __launch_bounds__(256)
void rgcn_gemm_kernel(const float* __restrict__ x,
                      const float* __restrict__ W,     // [R,128,128]
                      const float* __restrict__ root,  // [128,128]
                      const float* __restrict__ bias,
                      const float* __restrict__ gamma,
                      const float* __restrict__ beta,
                      float* __restrict__ out) {
    extern __shared__ float smem[];
    float* As = smem;                 // BM*DIM floats   (32 KB)
    float* Bs = smem + BM * DIM;      // DIM*DIM floats  (64 KB)

    int tid  = threadIdx.x;
    int row0 = blockIdx.x * BM;
    int ty   = tid >> 4;              // 0..15 -> rows ty*4..ty*4+3
    int tx   = tid & 15;              // 0..15 -> cols tx*8..tx*8+7

    unsigned long long acc[4][4];
#pragma unroll
    for (int i = 0; i < 4; i++)
#pragma unroll
        for (int j = 0; j < 4; j++) acc[i][j] = 0ull;

    for (int c = 0; c <= NREL; ++c) {
        // ---- load A tile (64 x 128), applying 1/cnt for relation chunks ----
#pragma unroll
        for (int l = 0; l < 8; ++l) {
            int idx = tid + l * 256;          // 0..2047 float4 slots
            int m   = idx >> 5;
            int k4  = idx & 31;
            int gr  = row0 + m;
            float4 v = make_float4(0.f, 0.f, 0.f, 0.f);
            if (gr < NNODES) {
                if (c < NREL) {
                    size_t seg = (size_t)gr * NREL + c;
                    float s = 1.0f / fmaxf(g_cnt[seg], 1.0f);
                    float4 vv = *(const float4*)(g_agg + seg * DIM + k4 * 4);
                    v.x = vv.x * s; v.y = vv.y * s; v.z = vv.z * s; v.w = vv.w * s;
                } else {
                    v = *(const float4*)(x + (size_t)gr * DIM + k4 * 4);
                }
            }
            *(float4*)(As + m * DIM + k4 * 4) = v;
        }
        // ---- load B tile (128 x 128) ----
        const float* Wr = (c < NREL) ? (W + (size_t)c * DIM * DIM) : root;
#pragma unroll
        for (int l = 0; l < 16; ++l) {
            int idx = tid + l * 256;          // 0..4095 float4 slots
            *(float4*)(Bs + idx * 4) = *(const float4*)(Wr + idx * 4);
        }
        __syncthreads();

        // ---- compute ----
#pragma unroll 8
        for (int k = 0; k < DIM; ++k) {
            unsigned a0 = __float_as_uint(As[(ty * 4 + 0) * DIM + k]);
            unsigned a1 = __float_as_uint(As[(ty * 4 + 1) * DIM + k]);
            unsigned a2 = __float_as_uint(As[(ty * 4 + 2) * DIM + k]);
            unsigned a3 = __float_as_uint(As[(ty * 4 + 3) * DIM + k]);
            unsigned long long p0, p1, p2, p3;
            asm("mov.b64 %0, {%1,%1};" : "=l"(p0) : "r"(a0));
            asm("mov.b64 %0, {%1,%1};" : "=l"(p1) : "r"(a1));
            asm("mov.b64 %0, {%1,%1};" : "=l"(p2) : "r"(a2));
            asm("mov.b64 %0, {%1,%1};" : "=l"(p3) : "r"(a3));
            ulonglong2 bA = *(const ulonglong2*)(Bs + k * DIM + tx * 8);
            ulonglong2 bB = *(const ulonglong2*)(Bs + k * DIM + tx * 8 + 4);
            unsigned long long b[4] = {bA.x, bA.y, bB.x, bB.y};
#pragma unroll
            for (int j = 0; j < 4; ++j) {
                asm("fma.rn.f32x2 %0, %1, %2, %0;" : "+l"(acc[0][j]) : "l"(p0), "l"(b[j]));
                asm("fma.rn.f32x2 %0, %1, %2, %0;" : "+l"(acc[1][j]) : "l"(p1), "l"(b[j]));
                asm("fma.rn.f32x2 %0, %1, %2, %0;" : "+l"(acc[2][j]) : "l"(p2), "l"(b[j]));
                asm("fma.rn.f32x2 %0, %1, %2, %0;" : "+l"(acc[3][j]) : "l"(p3), "l"(b[j]));
            }
        }
        __syncthreads();
    }

    // ---- epilogue: unpack + bias into Cs (reuse Bs), then LN/ReLU + store ----
    float* Cs = Bs;   // 64 x 128 fits in the 64 KB region
    float4 bv0 = *(const float4*)(bias + tx * 8);
    float4 bv1 = *(const float4*)(bias + tx * 8 + 4);
#pragma unroll
    for (int i = 0; i < 4; ++i) {
        float r[8];
#pragma unroll
        for (int j = 0; j < 4; ++j) {
            unsigned long long v = acc[i][j];
            r[j * 2]     = __uint_as_float((unsigned)(v & 0xffffffffull));
            r[j * 2 + 1] = __uint_as_float((unsigned)(v >> 32));
        }
        r[0] += bv0.x; r[1] += bv0.y; r[2] += bv0.z; r[3] += bv0.w;
        r[4] += bv1.x; r[5] += bv1.y; r[6] += bv1.z; r[7] += bv1.w;
        int m = ty * 4 + i;
        *(float4*)(Cs + m * DIM + tx * 8)     = make_float4(r[0], r[1], r[2], r[3]);
        *(float4*)(Cs + m * DIM + tx * 8 + 4) = make_float4(r[4], r[5], r[6], r[7]);
    }
    __syncthreads();

    int wid  = tid >> 5;
    int lane = tid & 31;
    float4 gm, bt;
    if (LN) {
        gm = *(const float4*)(gamma + lane * 4);
        bt = *(const float4*)(beta  + lane * 4);
    }
#pragma unroll
    for (int rr = 0; rr < 8; ++rr) {
        int m  = wid * 8 + rr;
        int gr = row0 + m;
        if (gr >= NNODES) continue;
        float4 v = *(float4*)(Cs + m * DIM + lane * 4);
        if (LN) {
            float s  = v.x + v.y + v.z + v.w;
            float sq = v.x * v.x + v.y * v.y + v.z * v.z + v.w * v.w;
#pragma unroll
            for (int off = 16; off > 0; off >>= 1) {
                s  += __shfl_xor_sync(0xffffffffu, s,  off);
                sq += __shfl_xor_sync(0xffffffffu, sq, off);
            }
            float mu  = s * (1.0f / DIM);
            float var = sq * (1.0f / DIM) - mu * mu;
            float inv = rsqrtf(var + LNEPS);
            v.x = fmaxf((v.x - mu) * inv * gm.x + bt.x, 0.f);
            v.y = fmaxf((v.y - mu) * inv * gm.y + bt.y, 0.f);
            v.z = fmaxf((v.z - mu) * inv * gm.z + bt.z, 0.f);
            v.w = fmaxf((v.w - mu) * inv * gm.w + bt.w, 0.f);
        }
        *(float4*)(out + (size_t)gr * DIM + lane * 4) = v;
    }
}

// ---------------- host side ----------------
static void run_layer(const float* xin, float* xout,
                      const float* W, const float* root, const float* bias,
                      const float* gamma, const float* beta, bool ln,
                      float* agg, float* cnt,
                      const int* edge_index, const int* edge_type) {
    const int agg4 = NNODES * NREL * DIM / 4;   // 12,800,000
    const int cnt4 = NNODES * NREL / 4;         // 100,000
    zero2_kernel<<<(agg4 + cnt4 + 255) / 256, 256>>>((float4*)agg, agg4, (float4*)cnt, cnt4);
    scatter_kernel<<<(NEDGES * 32 + 255) / 256, 256>>>(xin, edge_index, edge_type);
    int gblocks = (NNODES + BM - 1) / BM;
    size_t shmem = (size_t)(BM * DIM + DIM * DIM) * sizeof(float);  // 96 KB
    if (ln)
        rgcn_gemm_kernel<true><<<gblocks, 256, shmem>>>(xin, W, root, bias, gamma, beta, xout);
    else
        rgcn_gemm_kernel<false><<<gblocks, 256, shmem>>>(xin, W, root, bias, nullptr, nullptr, xout);
}

extern "C" void kernel_launch(void* const* d_in, const int* in_sizes, int n_in,
                              void* d_out, int out_size) {
    const int*   node_ids   = (const int*)d_in[0];
    const int*   edge_index = (const int*)d_in[1];
    const int*   edge_type  = (const int*)d_in[2];
    const float* emb        = (const float*)d_in[3];
    const float* W1    = (const float*)d_in[4];
    const float* root1 = (const float*)d_in[5];
    const float* b1    = (const float*)d_in[6];
    const float* g1    = (const float*)d_in[7];
    const float* be1   = (const float*)d_in[8];
    const float* W2    = (const float*)d_in[9];
    const float* root2 = (const float*)d_in[10];
    const float* b2    = (const float*)d_in[11];
    const float* g2    = (const float*)d_in[12];
    const float* be2   = (const float*)d_in[13];
    const float* W3    = (const float*)d_in[14];
    const float* root3 = (const float*)d_in[15];
    const float* b3    = (const float*)d_in[16];
    float* out = (float*)d_out;

    size_t shmem = (size_t)(BM * DIM + DIM * DIM) * sizeof(float);  // 96 KB
    cudaFuncSetAttribute((const void*)rgcn_gemm_kernel<true>,
                         cudaFuncAttributeMaxDynamicSharedMemorySize, (int)shmem);
    cudaFuncSetAttribute((const void*)rgcn_gemm_kernel<false>,
                         cudaFuncAttributeMaxDynamicSharedMemorySize, (int)shmem);

    float *xA, *xB, *agg, *cnt;
    cudaGetSymbolAddress((void**)&xA,  g_xA);
    cudaGetSymbolAddress((void**)&xB,  g_xB);
    cudaGetSymbolAddress((void**)&agg, g_agg);
    cudaGetSymbolAddress((void**)&cnt, g_cnt);

    // x0 = emb[node_ids]
    gather_kernel<<<(NNODES * 32 + 255) / 256, 256>>>(node_ids, (const float4*)emb, (float4*)xA);

    // layer 1: xA -> xB (LN+ReLU)
    run_layer(xA, xB, W1, root1, b1, g1, be1, true,  agg, cnt, edge_index, edge_type);
    // layer 2: xB -> xA (LN+ReLU)
    run_layer(xB, xA, W2, root2, b2, g2, be2, true,  agg, cnt, edge_index, edge_type);
    // layer 3: xA -> out (no LN)
    run_layer(xA, out, W3, root3, b3, nullptr, nullptr, false, agg, cnt, edge_index, edge_type);
}

// round 5
// speedup vs baseline: 1.0657x; 1.0657x over previous
#include <cuda_runtime.h>
#include <cstdint>
#include <cstddef>

#define NNODES 50000
#define NEDGES 800000
#define NREL   8
#define DIM    128
#define LNEPS  1e-5f
#define BM     128

// ---------------- scratch (device globals; no allocation allowed) ----------------
__device__ float g_xA[(size_t)NNODES * DIM];                 // 25.6 MB
__device__ float g_xB[(size_t)NNODES * DIM];                 // 25.6 MB
__device__ float g_agg[(size_t)NNODES * NREL * DIM];         // 204.8 MB
__device__ float g_cnt[(size_t)NNODES * NREL];               // 1.6 MB

// ---------------- utility kernels ----------------
__global__ void zero2_kernel(float4* __restrict__ a, int n4a,
                             float4* __restrict__ c, int n4c) {
    int i = blockIdx.x * blockDim.x + threadIdx.x;
    float4 z = make_float4(0.f, 0.f, 0.f, 0.f);
    if (i < n4a) a[i] = z;
    else if (i - n4a < n4c) c[i - n4a] = z;
}

__global__ void gather_kernel(const int* __restrict__ ids,
                              const float4* __restrict__ emb,
                              float4* __restrict__ x) {
    int i = blockIdx.x * blockDim.x + threadIdx.x;
    if (i >= NNODES * (DIM / 4)) return;
    int row = i >> 5;        // 32 float4 per row
    int c   = i & 31;
    x[(size_t)row * 32 + c] = emb[(size_t)ids[row] * 32 + c];
}

// One warp per edge: read 128 floats of x[src] (L2-resident), vector-reduce into agg.
__global__ void scatter_kernel(const float* __restrict__ x,
                               const int* __restrict__ ei,
                               const int* __restrict__ et) {
    int t = blockIdx.x * blockDim.x + threadIdx.x;
    int e = t >> 5;
    if (e >= NEDGES) return;
    int lane = t & 31;
    int src = ei[e];
    int dst = ei[NEDGES + e];
    int r   = et[e];
    size_t seg = (size_t)dst * NREL + r;
    float4 v = *(const float4*)(x + (size_t)src * DIM + lane * 4);
    float* p = g_agg + seg * DIM + lane * 4;
    asm volatile("red.global.add.v4.f32 [%0], {%1,%2,%3,%4};"
                 :: "l"(p), "f"(v.x), "f"(v.y), "f"(v.z), "f"(v.w) : "memory");
    if (lane == 0) atomicAdd(g_cnt + seg, 1.0f);
}

// ---------------- fused RGCN GEMM (+ optional LayerNorm+ReLU epilogue) ----------------
// out[n, :] = sum_{r<8} (agg[n,r,:]/max(cnt,1)) @ W[r] + x[n,:] @ root + bias
// Block tile 128x128, 256 threads, thread tile 8m x 8n (cols tx*4..+3 and 64+tx*4..+3).
// k unrolled by 4 so A rows load as LDS.128. Accumulators are f32x2 pairs along n.
template <bool LN>
__global__ __launch_bounds__(256)
void rgcn_gemm_kernel(const float* __restrict__ x,
                      const float* __restrict__ W,     // [R,128,128]
                      const float* __restrict__ root,  // [128,128]
                      const float* __restrict__ bias,
                      const float* __restrict__ gamma,
                      const float* __restrict__ beta,
                      float* __restrict__ out) {
    extern __shared__ float smem[];
    float* As = smem;                 // BM*DIM floats   (64 KB)
    float* Bs = smem + BM * DIM;      // DIM*DIM floats  (64 KB)

    int tid  = threadIdx.x;
    int row0 = blockIdx.x * BM;
    int ty   = tid >> 4;              // 0..15 -> rows ty*8 .. ty*8+7
    int tx   = tid & 15;              // 0..15 -> cols tx*4..+3 and 64+tx*4..+3

    // acc[i][j]: row i (0..7), n-pair j: j<2 -> cols tx*4+2j(+1); j>=2 -> 64+tx*4+2(j-2)(+1)
    unsigned long long acc[8][4];
#pragma unroll
    for (int i = 0; i < 8; i++)
#pragma unroll
        for (int j = 0; j < 4; j++) acc[i][j] = 0ull;

#pragma unroll 1
    for (int c = 0; c <= NREL; ++c) {
        __syncthreads();   // protect As/Bs from previous iteration's readers
        // ---- load A tile (128 x 128), applying 1/cnt for relation chunks ----
#pragma unroll
        for (int l = 0; l < 16; ++l) {
            int idx = tid + l * 256;          // 0..4095 float4 slots
            int m   = idx >> 5;
            int k4  = idx & 31;
            int gr  = row0 + m;
            float4 v = make_float4(0.f, 0.f, 0.f, 0.f);
            if (gr < NNODES) {
                if (c < NREL) {
                    size_t seg = (size_t)gr * NREL + c;
                    float s = 1.0f / fmaxf(g_cnt[seg], 1.0f);
                    float4 vv = *(const float4*)(g_agg + seg * DIM + k4 * 4);
                    v.x = vv.x * s; v.y = vv.y * s; v.z = vv.z * s; v.w = vv.w * s;
                } else {
                    v = *(const float4*)(x + (size_t)gr * DIM + k4 * 4);
                }
            }
            *(float4*)(As + m * DIM + k4 * 4) = v;
        }
        // ---- load B tile (128 x 128) ----
        const float* Wr = (c < NREL) ? (W + (size_t)c * DIM * DIM) : root;
#pragma unroll
        for (int l = 0; l < 16; ++l) {
            int idx = tid + l * 256;          // 0..4095 float4 slots
            *(float4*)(Bs + idx * 4) = *(const float4*)(Wr + idx * 4);
        }
        __syncthreads();

        // ---- compute: k in blocks of 4 ----
        const float4* As4 = (const float4*)As;
#pragma unroll 2
        for (int k4i = 0; k4i < DIM / 4; ++k4i) {
            float4 af[8];
#pragma unroll
            for (int i = 0; i < 8; i++)
                af[i] = As4[(ty * 8 + i) * (DIM / 4) + k4i];
#pragma unroll
            for (int kk = 0; kk < 4; ++kk) {
                const float* brow = Bs + (k4i * 4 + kk) * DIM;
                ulonglong2 b0 = *(const ulonglong2*)(brow + tx * 4);
                ulonglong2 b1 = *(const ulonglong2*)(brow + 64 + tx * 4);
                unsigned long long b[4] = {b0.x, b0.y, b1.x, b1.y};
#pragma unroll
                for (int i = 0; i < 8; i++) {
                    float a = (kk == 0) ? af[i].x : (kk == 1) ? af[i].y
                             : (kk == 2) ? af[i].z : af[i].w;
                    unsigned ai = __float_as_uint(a);
                    unsigned long long ad;
                    asm("mov.b64 %0, {%1,%1};" : "=l"(ad) : "r"(ai));
#pragma unroll
                    for (int j = 0; j < 4; j++)
                        asm("fma.rn.f32x2 %0, %1, %2, %0;"
                            : "+l"(acc[i][j]) : "l"(ad), "l"(b[j]));
                }
            }
        }
    }
    __syncthreads();   // done reading Bs; safe to reuse as Cs

    // ---- epilogue: unpack + bias into Cs (reuse Bs), then LN/ReLU + store ----
    float* Cs = Bs;   // 128 x 128 floats = 64 KB
    float4 bv0 = *(const float4*)(bias + tx * 4);
    float4 bv1 = *(const float4*)(bias + 64 + tx * 4);
#pragma unroll
    for (int i = 0; i < 8; ++i) {
        int m = ty * 8 + i;
        float r0[4], r1[4];
#pragma unroll
        for (int j = 0; j < 2; ++j) {
            r0[j * 2]     = __uint_as_float((unsigned)(acc[i][j] & 0xffffffffull));
            r0[j * 2 + 1] = __uint_as_float((unsigned)(acc[i][j] >> 32));
            r1[j * 2]     = __uint_as_float((unsigned)(acc[i][j + 2] & 0xffffffffull));
            r1[j * 2 + 1] = __uint_as_float((unsigned)(acc[i][j + 2] >> 32));
        }
        r0[0] += bv0.x; r0[1] += bv0.y; r0[2] += bv0.z; r0[3] += bv0.w;
        r1[0] += bv1.x; r1[1] += bv1.y; r1[2] += bv1.z; r1[3] += bv1.w;
        *(float4*)(Cs + m * DIM + tx * 4)      = make_float4(r0[0], r0[1], r0[2], r0[3]);
        *(float4*)(Cs + m * DIM + 64 + tx * 4) = make_float4(r1[0], r1[1], r1[2], r1[3]);
    }
    __syncthreads();

    int wid  = tid >> 5;
    int lane = tid & 31;
    float4 gm, bt;
    if (LN) {
        gm = *(const float4*)(gamma + lane * 4);
        bt = *(const float4*)(beta  + lane * 4);
    }
#pragma unroll 1
    for (int rr = 0; rr < BM / 8; ++rr) {       // 16 rows per warp
        int m  = wid * (BM / 8) + rr;
        int gr = row0 + m;
        if (gr >= NNODES) continue;
        float4 v = *(float4*)(Cs + m * DIM + lane * 4);
        if (LN) {
            float s  = v.x + v.y + v.z + v.w;
            float sq = v.x * v.x + v.y * v.y + v.z * v.z + v.w * v.w;
#pragma unroll
            for (int off = 16; off > 0; off >>= 1) {
                s  += __shfl_xor_sync(0xffffffffu, s,  off);
                sq += __shfl_xor_sync(0xffffffffu, sq, off);
            }
            float mu  = s * (1.0f / DIM);
            float var = sq * (1.0f / DIM) - mu * mu;
            float inv = rsqrtf(var + LNEPS);
            v.x = fmaxf((v.x - mu) * inv * gm.x + bt.x, 0.f);
            v.y = fmaxf((v.y - mu) * inv * gm.y + bt.y, 0.f);
            v.z = fmaxf((v.z - mu) * inv * gm.z + bt.z, 0.f);
            v.w = fmaxf((v.w - mu) * inv * gm.w + bt.w, 0.f);
        }
        *(float4*)(out + (size_t)gr * DIM + lane * 4) = v;
    }
}

// ---------------- host side ----------------
static void run_layer(const float* xin, float* xout,
                      const float* W, const float* root, const float* bias,
                      const float* gamma, const float* beta, bool ln,
                      float* agg, float* cnt,
                      const int* edge_index, const int* edge_type) {
    const int agg4 = NNODES * NREL * DIM / 4;   // 12,800,000
    const int cnt4 = NNODES * NREL / 4;         // 100,000
    zero2_kernel<<<(agg4 + cnt4 + 255) / 256, 256>>>((float4*)agg, agg4, (float4*)cnt, cnt4);
    scatter_kernel<<<(NEDGES * 32 + 255) / 256, 256>>>(xin, edge_index, edge_type);
    int gblocks = (NNODES + BM - 1) / BM;
    size_t shmem = (size_t)(BM * DIM + DIM * DIM) * sizeof(float);  // 128 KB
    if (ln)
        rgcn_gemm_kernel<true><<<gblocks, 256, shmem>>>(xin, W, root, bias, gamma, beta, xout);
    else
        rgcn_gemm_kernel<false><<<gblocks, 256, shmem>>>(xin, W, root, bias, nullptr, nullptr, xout);
}

extern "C" void kernel_launch(void* const* d_in, const int* in_sizes, int n_in,
                              void* d_out, int out_size) {
    const int*   node_ids   = (const int*)d_in[0];
    const int*   edge_index = (const int*)d_in[1];
    const int*   edge_type  = (const int*)d_in[2];
    const float* emb        = (const float*)d_in[3];
    const float* W1    = (const float*)d_in[4];
    const float* root1 = (const float*)d_in[5];
    const float* b1    = (const float*)d_in[6];
    const float* g1    = (const float*)d_in[7];
    const float* be1   = (const float*)d_in[8];
    const float* W2    = (const float*)d_in[9];
    const float* root2 = (const float*)d_in[10];
    const float* b2    = (const float*)d_in[11];
    const float* g2    = (const float*)d_in[12];
    const float* be2   = (const float*)d_in[13];
    const float* W3    = (const float*)d_in[14];
    const float* root3 = (const float*)d_in[15];
    const float* b3    = (const float*)d_in[16];
    float* out = (float*)d_out;

    size_t shmem = (size_t)(BM * DIM + DIM * DIM) * sizeof(float);  // 128 KB
    cudaFuncSetAttribute((const void*)rgcn_gemm_kernel<true>,
                         cudaFuncAttributeMaxDynamicSharedMemorySize, (int)shmem);
    cudaFuncSetAttribute((const void*)rgcn_gemm_kernel<false>,
                         cudaFuncAttributeMaxDynamicSharedMemorySize, (int)shmem);

    float *xA, *xB, *agg, *cnt;
    cudaGetSymbolAddress((void**)&xA,  g_xA);
    cudaGetSymbolAddress((void**)&xB,  g_xB);
    cudaGetSymbolAddress((void**)&agg, g_agg);
    cudaGetSymbolAddress((void**)&cnt, g_cnt);

    // x0 = emb[node_ids]
    gather_kernel<<<(NNODES * 32 + 255) / 256, 256>>>(node_ids, (const float4*)emb, (float4*)xA);

    // layer 1: xA -> xB (LN+ReLU)
    run_layer(xA, xB, W1, root1, b1, g1, be1, true,  agg, cnt, edge_index, edge_type);
    // layer 2: xB -> xA (LN+ReLU)
    run_layer(xB, xA, W2, root2, b2, g2, be2, true,  agg, cnt, edge_index, edge_type);
    // layer 3: xA -> out (no LN)
    run_layer(xA, out, W3, root3, b3, nullptr, nullptr, false, agg, cnt, edge_index, edge_type);
}